// round 5
// baseline (speedup 1.0000x reference)
#include <cuda_runtime.h>
#include <cstdint>

// Problem dims (fixed by the dataset problem)
#define RB 64      // batch
#define RT 512     // time steps
#define RI 128     // input dim
#define RH 512     // hidden dim
#define RO 64      // output dim

// ---------------------------------------------------------------------------
// Device scratch (allocation-free rule: __device__ globals)
// ---------------------------------------------------------------------------
__device__ float g_winT[RI * RH];                // W_in transposed: [I][H]
__device__ float g_xproj[(size_t)RB * RT * RH];  // [B][T][H] input projections
__device__ float g_hhist[(size_t)RB * RT * RH];  // [B][T][H] hidden states

// Packed fp32x2 helpers (Blackwell FFMA2 — ptxas never emits this from C++)
#define UPK2(lo, hi, src) \
    asm("mov.b64 {%0, %1}, %2;" : "=f"(lo), "=f"(hi) : "l"(src))
#define FMA2(acc, a, b) \
    asm("fma.rn.f32x2 %0, %1, %2, %0;" : "+l"(acc) : "l"(a), "l"(b))

// ---------------------------------------------------------------------------
// Kernel 0: transpose W_in [H][I] -> g_winT [I][H]  (tiny, 256 KB)
// ---------------------------------------------------------------------------
__global__ void k0_transpose(const float* __restrict__ W_in) {
    int idx = blockIdx.x * blockDim.x + threadIdx.x;   // 0 .. I*H-1
    int h = idx & (RH - 1);
    int i = idx >> 9;           // idx / RH
    g_winT[i * RH + h] = W_in[h * RI + i];
}

// ---------------------------------------------------------------------------
// Kernel 1: x_proj[b][t][h] = sum_i inputs[b][t][i] * W_in[h][i]
// Tiled fp32 GEMM: CTA = 64 rows (b,t) x 128 h-cols, K = 128 (one pass).
// ---------------------------------------------------------------------------
#define K1_SMEM_BYTES ((64 * 128 + 128 * 132) * 4)

__global__ void k1_xproj(const float* __restrict__ inp) {
    extern __shared__ float sm[];
    float* As = sm;                  // [64][128]
    float* Ws = sm + 64 * 128;       // [128][132] (padded, k-major)
    const int row0 = blockIdx.x * 64;   // row in [B*T)
    const int hc   = blockIdx.y * 128;  // h col base
    const int tid  = threadIdx.x;

    for (int idx = tid; idx < 64 * 128; idx += 256)
        As[idx] = inp[(size_t)row0 * RI + idx];     // rows contiguous
    for (int idx = tid; idx < 128 * 128; idx += 256) {
        int i = idx >> 7, h = idx & 127;
        Ws[i * 132 + h] = g_winT[i * RH + hc + h];
    }
    __syncthreads();

    const int colg = tid & 31;     // 32 col groups (h = colg + 32*j)
    const int warp = tid >> 5;     // 8 row groups (r = warp + 8*jr)
    float acc[8][4];
#pragma unroll
    for (int a = 0; a < 8; a++)
#pragma unroll
        for (int b = 0; b < 4; b++) acc[a][b] = 0.f;

#pragma unroll 4
    for (int k = 0; k < 128; k++) {
        float w[4], a[8];
#pragma unroll
        for (int j = 0; j < 4; j++) w[j] = Ws[k * 132 + colg + 32 * j];
#pragma unroll
        for (int jr = 0; jr < 8; jr++) a[jr] = As[(warp + 8 * jr) * 128 + k];
#pragma unroll
        for (int jr = 0; jr < 8; jr++)
#pragma unroll
            for (int j = 0; j < 4; j++) acc[jr][j] += a[jr] * w[j];
    }

#pragma unroll
    for (int jr = 0; jr < 8; jr++)
#pragma unroll
        for (int j = 0; j < 4; j++)
            g_xproj[(size_t)(row0 + warp + 8 * jr) * RH + hc + colg + 32 * j] = acc[jr][j];
}

// ---------------------------------------------------------------------------
// Kernel 2: the recurrent scan (cluster kernel).
// Grid: 128 CTAs = 16 clusters x 8 CTAs. Cluster c owns batch rows 4c..4c+3.
// CTA rank r owns hidden columns [64r, 64r+64); W_rec slice SMEM-resident.
// h (4x512, k-major) replicated per CTA, double-buffered by step parity.
//
// Per step:
//   0) warp-private expansion: hb[cur] -> hbd (h values duplicated in pairs),
//      __syncwarp only (each warp's GEMM k-range == its expansion range).
//   A) 4x64x512 GEMM, inner loop = 3x LDS.128 + 8x fma.rn.f32x2, zero movs.
//   B) k-slice reduction through SMEM, tanh.approx, leaky update.
//   C) staged exchange: local write of own contiguous 256-float chunk,
//      __syncthreads, then st.shared::cluster.v4 pushes to the 7 remote
//      CTAs (<=2 float4 per thread, mapa/offsets hoisted out of the loop).
//   D) one barrier.cluster (arrive=release / wait=acquire).
// ---------------------------------------------------------------------------
#define K2_WSTRIDE 72                          // floats per k-row of W slice (pad)
#define K2_HB_OFF  (512 * K2_WSTRIDE)          // 36864 floats
#define K2_HBD_OFF (K2_HB_OFF + 2 * 512 * 4)   // + hb double buffer (4096)
#define K2_RED_OFF (K2_HBD_OFF + 512 * 8)      // + duplicated-h buffer (4096)
#define K2_BS_OFF  (K2_RED_OFF + 16 * 256)     // + reduction buffer (4096)
#define K2_SMEM_FLOATS (K2_BS_OFF + 64)
#define K2_SMEM_BYTES (K2_SMEM_FLOATS * 4)     // 196864 B

__global__ void k2_rnn(const float* __restrict__ hidden,
                       const float* __restrict__ W_rec,
                       const float* __restrict__ bvec) {
    extern __shared__ float sm[];
    float* Wl  = sm;                    // [512][72]   W_rec slice, k-major
    float* hb  = sm + K2_HB_OFF;        // [2][512][4] h, k-major, b minor
    float* hbd = sm + K2_HBD_OFF;       // [512][8]    h duplicated pairs
    float* red = sm + K2_RED_OFF;       // [16][4][64] k-slice partials
    float* bs  = sm + K2_BS_OFF;        // [64] bias slice

    const int tid  = threadIdx.x;
    const unsigned rank = blockIdx.x & 7;     // == %cluster_ctarank for (8,1,1)
    const int b0  = (blockIdx.x >> 3) * 4;    // batch base for this cluster
    const int c0g = rank * 64;                // global col base for this CTA

    // Load W_rec slice, transposing to k-major (one-time)
    for (int idx = tid; idx < 64 * 512; idx += 256) {
        int c = idx >> 9, k = idx & 511;
        Wl[k * K2_WSTRIDE + c] = W_rec[(size_t)(c0g + c) * RH + k];
    }
    if (tid < 64) bs[tid] = bvec[c0g + tid];
    for (int idx = tid; idx < 2048; idx += 256) {
        int b = idx & 3, k = idx >> 2;
        hb[k * 4 + b] = hidden[(b0 + b) * RH + k];
    }
    __syncthreads();

    uint32_t smem_u32;
    asm("{ .reg .u64 t; cvta.to.shared.u64 t, %1; cvt.u32.u64 %0, t; }"
        : "=r"(smem_u32) : "l"(sm));
    const uint32_t hb_base = smem_u32 + (uint32_t)(K2_HB_OFF * 4);

    const int colg   = tid & 15;
    const int kslice = tid >> 4;
    const int kbase  = kslice * 32;
    const int ub  = tid >> 6;       // batch row for the epilogue (0..3) == push group
    const int uc  = tid & 63;       // local col for the epilogue (0..63) == push lane
    const int gcu = c0g + uc;       // global col
    const float bias = bs[uc];
    const float* xp_ptr = g_xproj + (size_t)(b0 + ub) * RT * RH + gcu;
    float*       hh_ptr = g_hhist + (size_t)(b0 + ub) * RT * RH + gcu;

    // expansion: warp w duplicates k in [64w, 64w+64), 2 k per lane
    const int we_k0 = (tid >> 5) * 64 + (tid & 31) * 2;

    // ---- hoisted DSMEM push targets ----
    // Thread (g=ub, lane64=uc) pushes chunk-float4 #uc to remote ranks
    // (rank+1+ub)&7 and, for ub<3, (rank+5+ub)&7: offsets {1..7}, each
    // remote covered by exactly one 64-thread group over all uc.
    const int r1 = ((int)rank + 1 + ub) & 7;
    const int r2 = ((int)rank + 1 + ub + 4) & 7;
    uint32_t rb1, rb2;
    asm("mapa.shared::cluster.u32 %0, %1, %2;" : "=r"(rb1) : "r"(hb_base), "r"(r1));
    asm("mapa.shared::cluster.u32 %0, %1, %2;" : "=r"(rb2) : "r"(hb_base), "r"(r2));
    const uint32_t choff = (uint32_t)((c0g * 4 + uc * 4) * 4); // byte off of this thread's float4
    const bool push2 = (ub < 3);

    float4* red4 = reinterpret_cast<float4*>(red);

    for (int t = 0; t < RT; t++) {
        const int cur = t & 1, nxt = cur ^ 1;

        // Prefetch this step's x_proj element (latency hides under GEMM)
        float xp = __ldg(xp_ptr + (size_t)t * RH);

        // ---- 0) warp-private h expansion: hb[cur] -> hbd (duplicated) ----
#pragma unroll
        for (int j = 0; j < 2; j++) {
            const int k = we_k0 + j;
            const float4 hv = *reinterpret_cast<const float4*>(hb + cur * 2048 + k * 4);
            float4 lo, hi;
            lo.x = hv.x; lo.y = hv.x; lo.z = hv.y; lo.w = hv.y;
            hi.x = hv.z; hi.y = hv.z; hi.z = hv.w; hi.w = hv.w;
            *reinterpret_cast<float4*>(hbd + k * 8)     = lo;
            *reinterpret_cast<float4*>(hbd + k * 8 + 4) = hi;
        }
        __syncwarp();

        // ---- A) GEMM, zero-mov inner loop ----
        uint64_t a0p0 = 0, a0p1 = 0, a1p0 = 0, a1p1 = 0;
        uint64_t a2p0 = 0, a2p1 = 0, a3p0 = 0, a3p1 = 0;
#pragma unroll 8
        for (int kk = 0; kk < 32; kk++) {
            const int k = kbase + kk;
            const ulonglong2 w  = *reinterpret_cast<const ulonglong2*>(
                Wl + k * K2_WSTRIDE + colg * 4);            // (w0,w1),(w2,w3)
            const ulonglong2 hA = *reinterpret_cast<const ulonglong2*>(
                hbd + k * 8);                               // (h0,h0),(h1,h1)
            const ulonglong2 hB = *reinterpret_cast<const ulonglong2*>(
                hbd + k * 8 + 4);                           // (h2,h2),(h3,h3)
            FMA2(a0p0, hA.x, w.x); FMA2(a0p1, hA.x, w.y);
            FMA2(a1p0, hA.y, w.x); FMA2(a1p1, hA.y, w.y);
            FMA2(a2p0, hB.x, w.x); FMA2(a2p1, hB.x, w.y);
            FMA2(a3p0, hB.y, w.x); FMA2(a3p1, hB.y, w.y);
        }
        // unpack and write k-slice partials: red[kslice][b][c0..c0+3]
        {
            float4 f;
            UPK2(f.x, f.y, a0p0); UPK2(f.z, f.w, a0p1);
            red4[kslice * 64 + 0 * 16 + colg] = f;
            UPK2(f.x, f.y, a1p0); UPK2(f.z, f.w, a1p1);
            red4[kslice * 64 + 1 * 16 + colg] = f;
            UPK2(f.x, f.y, a2p0); UPK2(f.z, f.w, a2p1);
            red4[kslice * 64 + 2 * 16 + colg] = f;
            UPK2(f.x, f.y, a3p0); UPK2(f.z, f.w, a3p1);
            red4[kslice * 64 + 3 * 16 + colg] = f;
        }
        __syncthreads();

        // ---- B) finalize one (b, col): reduce 16 slices ----
        float s = 0.f;
#pragma unroll
        for (int ss = 0; ss < 16; ss++) s += red[ss * 256 + ub * 64 + uc];
        const float pre  = s + xp + bias;
        float th;
        asm("tanh.approx.f32 %0, %1;" : "=f"(th) : "f"(pre));
        const float hold = hb[cur * 2048 + gcu * 4 + ub];
        const float hnew = 0.9f * hold + 0.1f * th;

        // Persist h state for the output pass (fire-and-forget)
        hh_ptr[(size_t)t * RH] = hnew;

        // ---- C) staged exchange ----
        hb[nxt * 2048 + gcu * 4 + ub] = hnew;     // local write of own element
        __syncthreads();
        // push the CTA's contiguous 256-float chunk to remote CTAs as float4
        {
            const float4 v = *reinterpret_cast<const float4*>(
                hb + nxt * 2048 + c0g * 4 + uc * 4);
            const uint32_t off = (uint32_t)(nxt * 2048 * 4) + choff;
            const uint32_t d1 = rb1 + off;
            asm volatile("st.shared::cluster.v4.f32 [%0], {%1,%2,%3,%4};"
                         :: "r"(d1), "f"(v.x), "f"(v.y), "f"(v.z), "f"(v.w) : "memory");
            if (push2) {
                const uint32_t d2 = rb2 + off;
                asm volatile("st.shared::cluster.v4.f32 [%0], {%1,%2,%3,%4};"
                             :: "r"(d2), "f"(v.x), "f"(v.y), "f"(v.z), "f"(v.w) : "memory");
            }
        }

        // ---- D) one cluster barrier per step ----
        asm volatile("barrier.cluster.arrive.aligned;" ::: "memory");
        asm volatile("barrier.cluster.wait.aligned;"   ::: "memory");
    }
}

// ---------------------------------------------------------------------------
// Kernel 3: out[b][t][o] = sum_h hhist[b][t][h] * W_out[o][h] + b_out[o]
// CTA = 128 rows x 32 o-cols; SMEM ~99 KB -> 2 CTAs/SM, 512 CTAs.
// ---------------------------------------------------------------------------
#define K3_WS 513
#define K3_AS 65
#define K3_SMEM_BYTES ((32 * K3_WS + 128 * K3_AS) * 4)

__global__ void k3_out(const float* __restrict__ W_out,
                       const float* __restrict__ b_out,
                       float* __restrict__ out) {
    extern __shared__ float sm[];
    float* Ws = sm;                   // [32][513]
    float* As = sm + 32 * K3_WS;      // [128][65]
    const int row0 = blockIdx.x * 128;
    const int ob0  = blockIdx.y * 32;  // o col base
    const int tid  = threadIdx.x;

    for (int idx = tid; idx < 32 * 512; idx += 256) {
        int o = idx >> 9, k = idx & 511;
        Ws[o * K3_WS + k] = W_out[(size_t)(ob0 + o) * RH + k];
    }

    const int og   = tid & 15;    // o = og + 16*j, j<2
    const int rowg = tid >> 4;    // r = rowg + 16*jr, jr<8
    float acc[8][2];
#pragma unroll
    for (int a = 0; a < 8; a++) { acc[a][0] = 0.f; acc[a][1] = 0.f; }

    for (int kc = 0; kc < 8; kc++) {
        __syncthreads();
        for (int idx = tid; idx < 128 * 64; idx += 256) {
            int r = idx >> 6, k = idx & 63;
            As[r * K3_AS + k] = g_hhist[(size_t)(row0 + r) * RH + kc * 64 + k];
        }
        __syncthreads();
#pragma unroll 4
        for (int kk = 0; kk < 64; kk++) {
            const int k = kc * 64 + kk;
            float w[2], a[8];
#pragma unroll
            for (int j = 0; j < 2; j++) w[j] = Ws[(og + 16 * j) * K3_WS + k];
#pragma unroll
            for (int jr = 0; jr < 8; jr++) a[jr] = As[(rowg + 16 * jr) * K3_AS + kk];
#pragma unroll
            for (int jr = 0; jr < 8; jr++)
#pragma unroll
                for (int j = 0; j < 2; j++) acc[jr][j] += a[jr] * w[j];
        }
    }

#pragma unroll
    for (int jr = 0; jr < 8; jr++)
#pragma unroll
        for (int j = 0; j < 2; j++)
            out[(size_t)(row0 + rowg + 16 * jr) * RO + ob0 + og + 16 * j] =
                acc[jr][j] + __ldg(&b_out[ob0 + og + 16 * j]);
}

// ---------------------------------------------------------------------------
// Kernel 4: h_final[b][h] = hhist[b][T-1][h]
// ---------------------------------------------------------------------------
__global__ void k4_hfinal(float* __restrict__ outh) {
    int idx = blockIdx.x * blockDim.x + threadIdx.x;   // 0 .. B*H-1
    int b = idx >> 9, h = idx & 511;
    outh[idx] = g_hhist[(size_t)b * RT * RH + (size_t)(RT - 1) * RH + h];
}

// ---------------------------------------------------------------------------
// Launch
// ---------------------------------------------------------------------------
extern "C" void kernel_launch(void* const* d_in, const int* in_sizes, int n_in,
                              void* d_out, int out_size) {
    const float* inputs = (const float*)d_in[0];
    const float* hidden = (const float*)d_in[1];
    const float* W_in   = (const float*)d_in[2];
    const float* W_rec  = (const float*)d_in[3];
    const float* bvec   = (const float*)d_in[4];
    const float* W_out  = (const float*)d_in[5];
    const float* b_out  = (const float*)d_in[6];
    float* out = (float*)d_out;

    cudaFuncSetAttribute(k1_xproj, cudaFuncAttributeMaxDynamicSharedMemorySize, K1_SMEM_BYTES);
    cudaFuncSetAttribute(k2_rnn,   cudaFuncAttributeMaxDynamicSharedMemorySize, K2_SMEM_BYTES);
    cudaFuncSetAttribute(k3_out,   cudaFuncAttributeMaxDynamicSharedMemorySize, K3_SMEM_BYTES);

    k0_transpose<<<(RI * RH) / 256, 256>>>(W_in);
    k1_xproj<<<dim3((RB * RT) / 64, RH / 128), 256, K1_SMEM_BYTES>>>(inputs);

    cudaLaunchConfig_t cfg = {};
    cfg.gridDim  = dim3(128, 1, 1);
    cfg.blockDim = dim3(256, 1, 1);
    cfg.dynamicSmemBytes = K2_SMEM_BYTES;
    cfg.stream = 0;
    cudaLaunchAttribute attrs[1];
    attrs[0].id = cudaLaunchAttributeClusterDimension;
    attrs[0].val.clusterDim.x = 8;
    attrs[0].val.clusterDim.y = 1;
    attrs[0].val.clusterDim.z = 1;
    cfg.attrs = attrs;
    cfg.numAttrs = 1;
    cudaLaunchKernelEx(&cfg, k2_rnn, hidden, W_rec, bvec);

    k3_out<<<dim3((RB * RT) / 128, RO / 32), 256, K3_SMEM_BYTES>>>(W_out, b_out, out);

    if (out_size >= RB * RT * RO + RB * RH)
        k4_hfinal<<<(RB * RH) / 256, 256>>>(out + (size_t)RB * RT * RO);
}

// round 7
// speedup vs baseline: 1.3620x; 1.3620x over previous
#include <cuda_runtime.h>
#include <cstdint>

// Problem dims (fixed by the dataset problem)
#define RB 64      // batch
#define RT 512     // time steps
#define RI 128     // input dim
#define RH 512     // hidden dim
#define RO 64      // output dim

// ---------------------------------------------------------------------------
// Device scratch (allocation-free rule: __device__ globals)
// ---------------------------------------------------------------------------
__device__ float g_winT[RI * RH];                // W_in transposed: [I][H]
__device__ float g_xproj[(size_t)RB * RT * RH];  // [B][T][H] input projections
__device__ float g_hhist[(size_t)RB * RT * RH];  // [B][T][H] hidden states

// Packed fp32x2 helpers (Blackwell FFMA2 — ptxas never emits this from C++)
#define PK2(dst, lo, hi) \
    asm("mov.b64 %0, {%1, %2};" : "=l"(dst) : "f"(lo), "f"(hi))
#define UPK2(lo, hi, src) \
    asm("mov.b64 {%0, %1}, %2;" : "=f"(lo), "=f"(hi) : "l"(src))
#define FMA2(acc, a, b) \
    asm("fma.rn.f32x2 %0, %1, %2, %0;" : "+l"(acc) : "l"(a), "l"(b))

// ---------------------------------------------------------------------------
// Kernel 0: transpose W_in [H][I] -> g_winT [I][H]  (tiny, 256 KB)
// ---------------------------------------------------------------------------
__global__ void k0_transpose(const float* __restrict__ W_in) {
    int idx = blockIdx.x * blockDim.x + threadIdx.x;   // 0 .. I*H-1
    int h = idx & (RH - 1);
    int i = idx >> 9;           // idx / RH
    g_winT[i * RH + h] = W_in[h * RI + i];
}

// ---------------------------------------------------------------------------
// Kernel 1: x_proj[b][t][h] = sum_i inputs[b][t][i] * W_in[h][i]
// Tiled fp32 GEMM: CTA = 64 rows (b,t) x 128 h-cols, K = 128 (one pass).
// ---------------------------------------------------------------------------
#define K1_SMEM_BYTES ((64 * 128 + 128 * 132) * 4)

__global__ void k1_xproj(const float* __restrict__ inp) {
    extern __shared__ float sm[];
    float* As = sm;                  // [64][128]
    float* Ws = sm + 64 * 128;       // [128][132] (padded, k-major)
    const int row0 = blockIdx.x * 64;   // row in [B*T)
    const int hc   = blockIdx.y * 128;  // h col base
    const int tid  = threadIdx.x;

    for (int idx = tid; idx < 64 * 128; idx += 256)
        As[idx] = inp[(size_t)row0 * RI + idx];     // rows contiguous
    for (int idx = tid; idx < 128 * 128; idx += 256) {
        int i = idx >> 7, h = idx & 127;
        Ws[i * 132 + h] = g_winT[i * RH + hc + h];
    }
    __syncthreads();

    const int colg = tid & 31;     // 32 col groups (h = colg + 32*j)
    const int warp = tid >> 5;     // 8 row groups (r = warp + 8*jr)
    float acc[8][4];
#pragma unroll
    for (int a = 0; a < 8; a++)
#pragma unroll
        for (int b = 0; b < 4; b++) acc[a][b] = 0.f;

#pragma unroll 4
    for (int k = 0; k < 128; k++) {
        float w[4], a[8];
#pragma unroll
        for (int j = 0; j < 4; j++) w[j] = Ws[k * 132 + colg + 32 * j];
#pragma unroll
        for (int jr = 0; jr < 8; jr++) a[jr] = As[(warp + 8 * jr) * 128 + k];
#pragma unroll
        for (int jr = 0; jr < 8; jr++)
#pragma unroll
            for (int j = 0; j < 4; j++) acc[jr][j] += a[jr] * w[j];
    }

#pragma unroll
    for (int jr = 0; jr < 8; jr++)
#pragma unroll
        for (int j = 0; j < 4; j++)
            g_xproj[(size_t)(row0 + warp + 8 * jr) * RH + hc + colg + 32 * j] = acc[jr][j];
}

// ---------------------------------------------------------------------------
// Kernel 2: the recurrent scan (cluster kernel).
// Grid: 128 CTAs = 16 clusters x 8 CTAs. Cluster c owns batch rows 4c..4c+3.
// CTA rank r owns hidden columns [64r, 64r+64).
//
// W is REGISTER-RESIDENT: each thread keeps its 4 cols x 32 k = 128 floats
// of the W_rec slice in 64 register pairs (ulonglong2 wr[32]) for all 512
// steps. The SMEM W slice is only a staging buffer at init. Inner loop per
// k: 1 broadcast LDS.128 of h + 4 dup-movs + 8 fma.rn.f32x2 — zero W loads.
//
// Per step:
//   A) 4x64x512 GEMM from registers (k split 16 ways).
//   B) k-slice reduction through SMEM, tanh.approx, leaky update.
//   C) staged exchange: local write of own contiguous 256-float chunk,
//      __syncthreads, then st.shared::cluster.v4 pushes to the 7 remote
//      CTAs (<=2 float4 per thread, mapa/offsets hoisted out of the loop).
//   D) one barrier.cluster (arrive=release / wait=acquire).
// ---------------------------------------------------------------------------
#define K2_WSTRIDE 72                          // floats per k-row of W staging (pad)
#define K2_HB_OFF  (512 * K2_WSTRIDE)          // 36864 floats
#define K2_RED_OFF (K2_HB_OFF + 2 * 512 * 4)   // + hb double buffer (4096)
#define K2_BS_OFF  (K2_RED_OFF + 16 * 256)     // + reduction buffer (4096)
#define K2_SMEM_FLOATS (K2_BS_OFF + 64)
#define K2_SMEM_BYTES (K2_SMEM_FLOATS * 4)     // 180480 B

__global__ void __launch_bounds__(256, 1)
k2_rnn(const float* __restrict__ hidden,
       const float* __restrict__ W_rec,
       const float* __restrict__ bvec) {
    extern __shared__ float sm[];
    float* Wl  = sm;                    // [512][72]   W staging (init only)
    float* hb  = sm + K2_HB_OFF;        // [2][512][4] h, k-major, b minor
    float* red = sm + K2_RED_OFF;       // [16][4][64] k-slice partials
    float* bs  = sm + K2_BS_OFF;        // [64] bias slice

    const int tid  = threadIdx.x;
    const unsigned rank = blockIdx.x & 7;     // == %cluster_ctarank for (8,1,1)
    const int b0  = (blockIdx.x >> 3) * 4;    // batch base for this cluster
    const int c0g = rank * 64;                // global col base for this CTA

    // Stage W_rec slice into SMEM, transposing to k-major (one-time)
    for (int idx = tid; idx < 64 * 512; idx += 256) {
        int c = idx >> 9, k = idx & 511;
        Wl[k * K2_WSTRIDE + c] = W_rec[(size_t)(c0g + c) * RH + k];
    }
    if (tid < 64) bs[tid] = bvec[c0g + tid];
    for (int idx = tid; idx < 2048; idx += 256) {
        int b = idx & 3, k = idx >> 2;
        hb[k * 4 + b] = hidden[(b0 + b) * RH + k];
    }
    __syncthreads();

    const int colg   = tid & 15;
    const int kslice = tid >> 4;
    const int kbase  = kslice * 32;

    // ---- pull this thread's W tile into registers (64 pairs = 128 regs) ----
    ulonglong2 wr[32];
#pragma unroll
    for (int kk = 0; kk < 32; kk++)
        wr[kk] = *reinterpret_cast<const ulonglong2*>(
            Wl + (kbase + kk) * K2_WSTRIDE + colg * 4);   // (w0,w1),(w2,w3)

    uint32_t smem_u32;
    asm("{ .reg .u64 t; cvta.to.shared.u64 t, %1; cvt.u32.u64 %0, t; }"
        : "=r"(smem_u32) : "l"(sm));
    const uint32_t hb_base = smem_u32 + (uint32_t)(K2_HB_OFF * 4);

    const int ub  = tid >> 6;       // batch row for the epilogue (0..3) == push group
    const int uc  = tid & 63;       // local col for the epilogue (0..63) == push lane
    const int gcu = c0g + uc;       // global col
    const float bias = bs[uc];
    const float* xp_ptr = g_xproj + (size_t)(b0 + ub) * RT * RH + gcu;
    float*       hh_ptr = g_hhist + (size_t)(b0 + ub) * RT * RH + gcu;

    // ---- hoisted DSMEM push targets ----
    // Thread (g=ub, lane64=uc) pushes chunk-float4 #uc to remote ranks
    // (rank+1+ub)&7 and, for ub<3, (rank+5+ub)&7: offsets {1..7}, each
    // remote covered by exactly one 64-thread group over all uc.
    const int r1 = ((int)rank + 1 + ub) & 7;
    const int r2 = ((int)rank + 1 + ub + 4) & 7;
    uint32_t rb1, rb2;
    asm("mapa.shared::cluster.u32 %0, %1, %2;" : "=r"(rb1) : "r"(hb_base), "r"(r1));
    asm("mapa.shared::cluster.u32 %0, %1, %2;" : "=r"(rb2) : "r"(hb_base), "r"(r2));
    const uint32_t choff = (uint32_t)((c0g * 4 + uc * 4) * 4); // byte off of this thread's float4
    const bool push2 = (ub < 3);

    float4* red4 = reinterpret_cast<float4*>(red);

    for (int t = 0; t < RT; t++) {
        const int cur = t & 1, nxt = cur ^ 1;
        const float4* h4 = reinterpret_cast<const float4*>(hb + cur * 2048 + kbase * 4);

        // Prefetch this step's x_proj element (latency hides under GEMM)
        float xp = __ldg(xp_ptr + (size_t)t * RH);

        // ---- A) GEMM from register-resident W ----
        uint64_t a0p0 = 0, a0p1 = 0, a1p0 = 0, a1p1 = 0;
        uint64_t a2p0 = 0, a2p1 = 0, a3p0 = 0, a3p1 = 0;
#pragma unroll
        for (int kk = 0; kk < 32; kk++) {
            const float4 hv = h4[kk];          // broadcast LDS.128
            uint64_t hd0, hd1, hd2, hd3;
            PK2(hd0, hv.x, hv.x);
            PK2(hd1, hv.y, hv.y);
            PK2(hd2, hv.z, hv.z);
            PK2(hd3, hv.w, hv.w);
            FMA2(a0p0, hd0, wr[kk].x); FMA2(a0p1, hd0, wr[kk].y);
            FMA2(a1p0, hd1, wr[kk].x); FMA2(a1p1, hd1, wr[kk].y);
            FMA2(a2p0, hd2, wr[kk].x); FMA2(a2p1, hd2, wr[kk].y);
            FMA2(a3p0, hd3, wr[kk].x); FMA2(a3p1, hd3, wr[kk].y);
        }
        // unpack and write k-slice partials: red[kslice][b][c0..c0+3]
        {
            float4 f;
            UPK2(f.x, f.y, a0p0); UPK2(f.z, f.w, a0p1);
            red4[kslice * 64 + 0 * 16 + colg] = f;
            UPK2(f.x, f.y, a1p0); UPK2(f.z, f.w, a1p1);
            red4[kslice * 64 + 1 * 16 + colg] = f;
            UPK2(f.x, f.y, a2p0); UPK2(f.z, f.w, a2p1);
            red4[kslice * 64 + 2 * 16 + colg] = f;
            UPK2(f.x, f.y, a3p0); UPK2(f.z, f.w, a3p1);
            red4[kslice * 64 + 3 * 16 + colg] = f;
        }
        __syncthreads();

        // ---- B) finalize one (b, col): reduce 16 slices ----
        float s = 0.f;
#pragma unroll
        for (int ss = 0; ss < 16; ss++) s += red[ss * 256 + ub * 64 + uc];
        const float pre  = s + xp + bias;
        float th;
        asm("tanh.approx.f32 %0, %1;" : "=f"(th) : "f"(pre));
        const float hold = hb[cur * 2048 + gcu * 4 + ub];
        const float hnew = 0.9f * hold + 0.1f * th;

        // Persist h state for the output pass (fire-and-forget)
        hh_ptr[(size_t)t * RH] = hnew;

        // ---- C) staged exchange ----
        hb[nxt * 2048 + gcu * 4 + ub] = hnew;     // local write of own element
        __syncthreads();
        // push the CTA's contiguous 256-float chunk to remote CTAs as float4
        {
            const float4 v = *reinterpret_cast<const float4*>(
                hb + nxt * 2048 + c0g * 4 + uc * 4);
            const uint32_t off = (uint32_t)(nxt * 2048 * 4) + choff;
            const uint32_t d1 = rb1 + off;
            asm volatile("st.shared::cluster.v4.f32 [%0], {%1,%2,%3,%4};"
                         :: "r"(d1), "f"(v.x), "f"(v.y), "f"(v.z), "f"(v.w) : "memory");
            if (push2) {
                const uint32_t d2 = rb2 + off;
                asm volatile("st.shared::cluster.v4.f32 [%0], {%1,%2,%3,%4};"
                             :: "r"(d2), "f"(v.x), "f"(v.y), "f"(v.z), "f"(v.w) : "memory");
            }
        }

        // ---- D) one cluster barrier per step ----
        asm volatile("barrier.cluster.arrive.aligned;" ::: "memory");
        asm volatile("barrier.cluster.wait.aligned;"   ::: "memory");
    }
}

// ---------------------------------------------------------------------------
// Kernel 3: out[b][t][o] = sum_h hhist[b][t][h] * W_out[o][h] + b_out[o]
// CTA = 128 rows x 32 o-cols; SMEM ~99 KB -> 2 CTAs/SM, 512 CTAs.
// ---------------------------------------------------------------------------
#define K3_WS 513
#define K3_AS 65
#define K3_SMEM_BYTES ((32 * K3_WS + 128 * K3_AS) * 4)

__global__ void k3_out(const float* __restrict__ W_out,
                       const float* __restrict__ b_out,
                       float* __restrict__ out) {
    extern __shared__ float sm[];
    float* Ws = sm;                   // [32][513]
    float* As = sm + 32 * K3_WS;      // [128][65]
    const int row0 = blockIdx.x * 128;
    const int ob0  = blockIdx.y * 32;  // o col base
    const int tid  = threadIdx.x;

    for (int idx = tid; idx < 32 * 512; idx += 256) {
        int o = idx >> 9, k = idx & 511;
        Ws[o * K3_WS + k] = W_out[(size_t)(ob0 + o) * RH + k];
    }

    const int og   = tid & 15;    // o = og + 16*j, j<2
    const int rowg = tid >> 4;    // r = rowg + 16*jr, jr<8
    float acc[8][2];
#pragma unroll
    for (int a = 0; a < 8; a++) { acc[a][0] = 0.f; acc[a][1] = 0.f; }

    for (int kc = 0; kc < 8; kc++) {
        __syncthreads();
        for (int idx = tid; idx < 128 * 64; idx += 256) {
            int r = idx >> 6, k = idx & 63;
            As[r * K3_AS + k] = g_hhist[(size_t)(row0 + r) * RH + kc * 64 + k];
        }
        __syncthreads();
#pragma unroll 4
        for (int kk = 0; kk < 64; kk++) {
            const int k = kc * 64 + kk;
            float w[2], a[8];
#pragma unroll
            for (int j = 0; j < 2; j++) w[j] = Ws[(og + 16 * j) * K3_WS + k];
#pragma unroll
            for (int jr = 0; jr < 8; jr++) a[jr] = As[(rowg + 16 * jr) * K3_AS + kk];
#pragma unroll
            for (int jr = 0; jr < 8; jr++)
#pragma unroll
                for (int j = 0; j < 2; j++) acc[jr][j] += a[jr] * w[j];
        }
    }

#pragma unroll
    for (int jr = 0; jr < 8; jr++)
#pragma unroll
        for (int j = 0; j < 2; j++)
            out[(size_t)(row0 + rowg + 16 * jr) * RO + ob0 + og + 16 * j] =
                acc[jr][j] + __ldg(&b_out[ob0 + og + 16 * j]);
}

// ---------------------------------------------------------------------------
// Kernel 4: h_final[b][h] = hhist[b][T-1][h]
// ---------------------------------------------------------------------------
__global__ void k4_hfinal(float* __restrict__ outh) {
    int idx = blockIdx.x * blockDim.x + threadIdx.x;   // 0 .. B*H-1
    int b = idx >> 9, h = idx & 511;
    outh[idx] = g_hhist[(size_t)b * RT * RH + (size_t)(RT - 1) * RH + h];
}

// ---------------------------------------------------------------------------
// Launch
// ---------------------------------------------------------------------------
extern "C" void kernel_launch(void* const* d_in, const int* in_sizes, int n_in,
                              void* d_out, int out_size) {
    const float* inputs = (const float*)d_in[0];
    const float* hidden = (const float*)d_in[1];
    const float* W_in   = (const float*)d_in[2];
    const float* W_rec  = (const float*)d_in[3];
    const float* bvec   = (const float*)d_in[4];
    const float* W_out  = (const float*)d_in[5];
    const float* b_out  = (const float*)d_in[6];
    float* out = (float*)d_out;

    cudaFuncSetAttribute(k1_xproj, cudaFuncAttributeMaxDynamicSharedMemorySize, K1_SMEM_BYTES);
    cudaFuncSetAttribute(k2_rnn,   cudaFuncAttributeMaxDynamicSharedMemorySize, K2_SMEM_BYTES);
    cudaFuncSetAttribute(k3_out,   cudaFuncAttributeMaxDynamicSharedMemorySize, K3_SMEM_BYTES);

    k0_transpose<<<(RI * RH) / 256, 256>>>(W_in);
    k1_xproj<<<dim3((RB * RT) / 64, RH / 128), 256, K1_SMEM_BYTES>>>(inputs);

    cudaLaunchConfig_t cfg = {};
    cfg.gridDim  = dim3(128, 1, 1);
    cfg.blockDim = dim3(256, 1, 1);
    cfg.dynamicSmemBytes = K2_SMEM_BYTES;
    cfg.stream = 0;
    cudaLaunchAttribute attrs[1];
    attrs[0].id = cudaLaunchAttributeClusterDimension;
    attrs[0].val.clusterDim.x = 8;
    attrs[0].val.clusterDim.y = 1;
    attrs[0].val.clusterDim.z = 1;
    cfg.attrs = attrs;
    cfg.numAttrs = 1;
    cudaLaunchKernelEx(&cfg, k2_rnn, hidden, W_rec, bvec);

    k3_out<<<dim3((RB * RT) / 128, RO / 32), 256, K3_SMEM_BYTES>>>(W_out, b_out, out);

    if (out_size >= RB * RT * RO + RB * RH)
        k4_hfinal<<<(RB * RH) / 256, 256>>>(out + (size_t)RB * RT * RO);
}